// round 9
// baseline (speedup 1.0000x reference)
#include <cuda_runtime.h>
#include <cuda_fp16.h>
#include <cstdint>

#define BATCH 4096
#define OBS 16
#define TDEC 32
#define H 512
#define NG 2048
#define KC 64
#define NSTAGE 8             // 512/64
#define DEPTH 3
#define BM 128
#define BN 128
#define THREADS 256
#define NJOBS 1024           // 16 nx * 32 my * 2 z
#define GRID 296
#define STAGE_BYTES 32768    // A 16K | B 16K
#define DYN_SMEM (DEPTH * STAGE_BYTES)   // 98304

// ---------------- device state ----------------
__device__ __align__(16) float   g_h[2][BATCH * H];        // fp32 h (combine only)
__device__ __align__(16) float   g_c[2][BATCH * H];
__device__ __align__(16) __half  g_hh[2][2][BATCH * H];    // fp16 h, [slot][parity]
__device__ __align__(16) __half  g_Ws[4][NG * 512];        // [(4u+g)][k] fp16
__device__ __align__(16) float   g_Wi[4][NG * 4];
__device__ __align__(16) float   g_bb[4][NG];
__device__ __align__(16) float   g_ls[BATCH * 4];
__device__ __align__(16) float   g_lp[BATCH * 4];
__device__ unsigned              g_job[64];

// ---------------- helpers ----------------
__device__ __forceinline__ unsigned su32(const void* p) {
    return (unsigned)__cvta_generic_to_shared(p);
}
__device__ __forceinline__ void cp16(unsigned d, const void* s) {
    asm volatile("cp.async.cg.shared.global [%0], [%1], 16;" :: "r"(d), "l"(s));
}
__device__ __forceinline__ unsigned swz(unsigned o) { return o ^ ((o >> 3) & 0x70); }
__device__ __forceinline__ float sigf(float x) { return 1.f / (1.f + __expf(-x)); }
__device__ __forceinline__ float tanhfast(float x) { return 2.f / (1.f + __expf(-2.f * x)) - 1.f; }

// ---------------- weight prep ----------------
struct WPtrs { const float* Wh[4]; const float* Wi[4]; const float* bb[4]; };

__global__ void prep_weights(WPtrs p) {
    int k = threadIdx.x, j = blockIdx.x, l = blockIdx.y;
    float w = p.Wh[l][j * H + k];
    int pr = 4 * (j & (H - 1)) + (j >> 9);   // 4u + gate
    g_Ws[l][pr * 512 + k] = __float2half(w);
    if (k < 4)  g_Wi[l][pr * 4 + k] = p.Wi[l][j * 4 + k];
    if (k == 0) g_bb[l][pr] = p.bb[l][j];
}

__global__ void init_state(const float* speed, const float* pos) {
    int idx = blockIdx.x * blockDim.x + threadIdx.x;
    if (idx < 2 * BATCH * H) {
        int s = idx / (BATCH * H), i = idx % (BATCH * H);
        g_h[s][i] = 0.f; g_c[s][i] = 0.f;
        g_hh[s][0][i] = __float2half(0.f);
    }
    if (idx < BATCH * 4) {
        int b = idx >> 2, k = idx & 3;
        g_ls[idx] = speed[b * (OBS * 4) + (OBS - 1) * 4 + k];
        g_lp[idx] = pos[b * (OBS * 4) + (OBS - 1) * 4 + k];
    }
    if (idx < 64) g_job[idx] = 0;
}

__global__ void combine_state() {
    int i = blockIdx.x * blockDim.x + threadIdx.x;
    float hs = g_h[0][i] + g_h[1][i];
    float cs = g_c[0][i] + g_c[1][i];
    g_c[0][i] = cs; g_c[1][i] = cs;
    __half hv = __float2half(hs);
    g_hh[0][0][i] = hv; g_hh[1][0][i] = hv;
}

// ---------------- fused LSTM cell: persistent, fp16 mma.sync, 128x128 tiles ----------------
__global__ void __launch_bounds__(THREADS, 2) lstm_cell(
    int lstm_base, const float* x0, const float* x1, int xstride, int internal_x,
    int rp, int jid, int write_h32)
{
    extern __shared__ char smem[];
    __shared__ float sB[BN];
    __shared__ float sWi[BN * 4];
    __shared__ int sjob;

    const int tid = threadIdx.x;
    const int lane = tid & 31, warp = tid >> 5;
    const int wmb = (warp & 1) * 64;   // warp m base
    const int wnb = (warp >> 1) * 32;  // warp n base
    const int wp = 1 - rp;

    for (;;) {
        __syncthreads();
        if (tid == 0) sjob = (int)atomicAdd(&g_job[jid], 1u);
        __syncthreads();
        const int j = sjob;
        if (j >= NJOBS) break;

        const int nx = j & 15;
        const int rest = j >> 4;
        const int z = rest & 1;
        const int my = rest >> 1;
        const int n0 = nx * BN, m0 = my * BM;
        const int lstm = lstm_base + z;

        const float* x = internal_x ? (z ? g_lp : g_ls) : (z ? x1 : x0);
        const __half* hh = g_hh[z][rp];
        const __half* Wsp = g_Ws[lstm];

        if (tid < BN) {
            int n = n0 + tid;
            sB[tid] = g_bb[lstm][n];
            #pragma unroll
            for (int k = 0; k < 4; k++) sWi[tid * 4 + k] = g_Wi[lstm][n * 4 + k];
        }

        float acc[4][4][4] = {};

        auto produce = [&](int sp) {
            int kc = sp * KC;
            unsigned sbase = (unsigned)((sp % DEPTH) * STAGE_BYTES);
            #pragma unroll
            for (int r = 0; r < 4; r++) {
                int idx = tid + r * THREADS;
                int row = idx >> 3, seg = idx & 7;
                cp16(su32(smem + sbase + swz(row * 128 + seg * 16)),
                     hh + (size_t)(m0 + row) * 512 + kc + seg * 8);
            }
            #pragma unroll
            for (int r = 0; r < 4; r++) {
                int idx = tid + r * THREADS;
                int row = idx >> 3, seg = idx & 7;
                cp16(su32(smem + sbase + 16384 + swz(row * 128 + seg * 16)),
                     Wsp + (size_t)(n0 + row) * 512 + kc + seg * 8);
            }
            asm volatile("cp.async.commit_group;");
        };

        produce(0);
        produce(1);

        for (int s = 0; s < NSTAGE; s++) {
            if (s == NSTAGE - 1) asm volatile("cp.async.wait_group 0;");
            else                 asm volatile("cp.async.wait_group 1;");
            __syncthreads();
            if (s + 2 < NSTAGE) produce(s + 2);

            const char* Ab = smem + (s % DEPTH) * STAGE_BYTES;
            const char* Bb = Ab + 16384;

            uint32_t afr[2][4][4];
            auto lda = [&](int buf, int kkv) {
                #pragma unroll
                for (int im = 0; im < 4; im++) {
                    int row = wmb + im * 16 + (lane & 15);
                    unsigned off = swz(row * 128 + kkv * 32 + ((lane >> 4) << 4));
                    asm volatile("ldmatrix.sync.aligned.m8n8.x4.shared.b16 {%0,%1,%2,%3}, [%4];"
                        : "=r"(afr[buf][im][0]), "=r"(afr[buf][im][1]),
                          "=r"(afr[buf][im][2]), "=r"(afr[buf][im][3])
                        : "r"(su32(Ab + off)));
                }
            };

            lda(0, 0);
            #pragma unroll
            for (int kk = 0; kk < 4; kk++) {
                uint32_t b[4][2];
                #pragma unroll
                for (int gp = 0; gp < 2; gp++) {
                    int row = wnb + gp * 16 + ((lane >> 4) << 3) + (lane & 7);
                    unsigned off = swz(row * 128 + kk * 32 + (((lane >> 3) & 1) << 4));
                    asm volatile("ldmatrix.sync.aligned.m8n8.x4.shared.b16 {%0,%1,%2,%3}, [%4];"
                        : "=r"(b[2 * gp][0]), "=r"(b[2 * gp][1]),
                          "=r"(b[2 * gp + 1][0]), "=r"(b[2 * gp + 1][1])
                        : "r"(su32(Bb + off)));
                }
                if (kk < 3) lda((kk + 1) & 1, kk + 1);
                const int cb = kk & 1;
                #pragma unroll
                for (int im = 0; im < 4; im++)
                    #pragma unroll
                    for (int g = 0; g < 4; g++)
                        asm volatile("mma.sync.aligned.m16n8k16.row.col.f32.f16.f16.f32 "
                            "{%0,%1,%2,%3}, {%4,%5,%6,%7}, {%8,%9}, {%0,%1,%2,%3};"
                            : "+f"(acc[im][g][0]), "+f"(acc[im][g][1]),
                              "+f"(acc[im][g][2]), "+f"(acc[im][g][3])
                            : "r"(afr[cb][im][0]), "r"(afr[cb][im][1]),
                              "r"(afr[cb][im][2]), "r"(afr[cb][im][3]),
                              "r"(b[g][0]), "r"(b[g][1]));
            }
        }

        // ---------------- epilogue ----------------
        float* Gs = (float*)smem;   // [128][132]
        __syncthreads();
        #pragma unroll
        for (int im = 0; im < 4; im++)
            #pragma unroll
            for (int g = 0; g < 4; g++) {
                int r = wmb + im * 16 + (lane >> 2);
                int c = wnb + g * 8 + 2 * (lane & 3);
                Gs[r * 132 + c]           = acc[im][g][0];
                Gs[r * 132 + c + 1]       = acc[im][g][1];
                Gs[(r + 8) * 132 + c]     = acc[im][g][2];
                Gs[(r + 8) * 132 + c + 1] = acc[im][g][3];
            }
        __syncthreads();

        float* hout = g_h[z];
        float* cio  = g_c[z];
        __half* hhw = g_hh[z][wp];
        const int u0g = n0 >> 2;

        #pragma unroll 4
        for (int i = 0; i < 16; i++) {
            int p = tid + THREADS * i;
            int m = p >> 5, ul = p & 31;
            int mg = m0 + m;
            const float4 gv = *(const float4*)&Gs[m * 132 + 4 * ul];
            const float* xr = x + (size_t)mg * xstride;
            float xv0 = xr[0], xv1 = xr[1], xv2 = xr[2], xv3 = xr[3];
            float gate[4] = { gv.x, gv.y, gv.z, gv.w };
            #pragma unroll
            for (int q = 0; q < 4; q++) {
                int nn = 4 * ul + q;
                gate[q] += sB[nn] + xv0 * sWi[nn * 4 + 0] + xv1 * sWi[nn * 4 + 1]
                                  + xv2 * sWi[nn * 4 + 2] + xv3 * sWi[nn * 4 + 3];
            }
            float iv = sigf(gate[0]);
            float fv = sigf(gate[1]);
            float gg = tanhfast(gate[2]);
            float ov = sigf(gate[3]);
            size_t ci = (size_t)mg * H + u0g + ul;
            float cn = fv * cio[ci] + iv * gg;
            float hn = ov * tanhfast(cn);
            cio[ci] = cn;
            if (write_h32) hout[ci] = hn;
            hhw[ci] = __float2half(hn);
        }
    }
}

// ---------------- decoder projections + feedback (fp16 h inputs) ----------------
__global__ void proj_kernel(const float* W_fs, const float* b_fs,
                            const float* W_fc, const float* b_fc,
                            const float* W_emb, const float* b_emb,
                            float* out, int t, int par)
{
    int warp = threadIdx.x >> 5, lane = threadIdx.x & 31;
    int b = blockIdx.x * 8 + warp;
    float a0 = 0, a1 = 0, a2 = 0, a3 = 0, a4 = 0, a5 = 0;
    const __half2* hs = (const __half2*)(g_hh[0][par] + (size_t)b * H);
    const __half2* hi = (const __half2*)(g_hh[1][par] + (size_t)b * H);
    for (int k2 = lane; k2 < H / 2; k2 += 32) {
        float2 vs = __half22float2(hs[k2]);
        float2 vi = __half22float2(hi[k2]);
        int k = 2 * k2;
        a0 += vs.x * W_fs[k]         + vs.y * W_fs[k + 1];
        a1 += vs.x * W_fs[H + k]     + vs.y * W_fs[H + k + 1];
        a2 += vs.x * W_fs[2 * H + k] + vs.y * W_fs[2 * H + k + 1];
        a3 += vs.x * W_fs[3 * H + k] + vs.y * W_fs[3 * H + k + 1];
        a4 += vi.x * W_fc[k]         + vi.y * W_fc[k + 1];
        a5 += vi.x * W_fc[H + k]     + vi.y * W_fc[H + k + 1];
    }
    #pragma unroll
    for (int o = 16; o; o >>= 1) {
        a0 += __shfl_down_sync(0xffffffffu, a0, o);
        a1 += __shfl_down_sync(0xffffffffu, a1, o);
        a2 += __shfl_down_sync(0xffffffffu, a2, o);
        a3 += __shfl_down_sync(0xffffffffu, a3, o);
        a4 += __shfl_down_sync(0xffffffffu, a4, o);
        a5 += __shfl_down_sync(0xffffffffu, a5, o);
    }
    if (lane == 0) {
        float4 spv;
        spv.x = fminf(fmaxf(a0 + b_fs[0], -100.f), 100.f);
        spv.y = fminf(fmaxf(a1 + b_fs[1], -100.f), 100.f);
        spv.z = fminf(fmaxf(a2 + b_fs[2], -100.f), 100.f);
        spv.w = fminf(fmaxf(a3 + b_fs[3], -100.f), 100.f);
        float it0 = fmaxf(a4 + b_fc[0], 0.f);
        float it1 = fmaxf(a5 + b_fc[1], 0.f);
        *(float4*)&out[((size_t)b * TDEC + t) * 4] = spv;
        *(float4*)&g_ls[b * 4] = spv;
        float4 lpv;
        lpv.x = fmaxf(W_emb[0] * it0 + W_emb[1] * it1 + b_emb[0], 0.f);
        lpv.y = fmaxf(W_emb[2] * it0 + W_emb[3] * it1 + b_emb[1], 0.f);
        lpv.z = fmaxf(W_emb[4] * it0 + W_emb[5] * it1 + b_emb[2], 0.f);
        lpv.w = fmaxf(W_emb[6] * it0 + W_emb[7] * it1 + b_emb[3], 0.f);
        *(float4*)&g_lp[b * 4] = lpv;
        if (t == TDEC - 1) {
            float mx = fmaxf(it0, it1);
            float e0 = expf(it0 - mx), e1 = expf(it1 - mx);
            float s = e0 + e1;
            out[(size_t)BATCH * TDEC * 4 + b * 2]     = e0 / s;
            out[(size_t)BATCH * TDEC * 4 + b * 2 + 1] = e1 / s;
        }
    }
}

// ---------------- launch ----------------
extern "C" void kernel_launch(void* const* d_in, const int* in_sizes, int n_in,
                              void* d_out, int out_size)
{
    const float* speed = (const float*)d_in[0];
    const float* pos   = (const float*)d_in[1];
    WPtrs wpt;
    wpt.Wi[0] = (const float*)d_in[2];  wpt.Wh[0] = (const float*)d_in[3];  wpt.bb[0] = (const float*)d_in[4];
    wpt.Wi[1] = (const float*)d_in[5];  wpt.Wh[1] = (const float*)d_in[6];  wpt.bb[1] = (const float*)d_in[7];
    wpt.Wi[2] = (const float*)d_in[8];  wpt.Wh[2] = (const float*)d_in[9];  wpt.bb[2] = (const float*)d_in[10];
    wpt.Wi[3] = (const float*)d_in[11]; wpt.Wh[3] = (const float*)d_in[12]; wpt.bb[3] = (const float*)d_in[13];
    const float* W_fs  = (const float*)d_in[14];
    const float* b_fs  = (const float*)d_in[15];
    const float* W_fc  = (const float*)d_in[16];
    const float* b_fc  = (const float*)d_in[17];
    const float* W_emb = (const float*)d_in[18];
    const float* b_emb = (const float*)d_in[19];
    float* out = (float*)d_out;

    cudaFuncSetAttribute(lstm_cell, cudaFuncAttributeMaxDynamicSharedMemorySize, DYN_SMEM);

    prep_weights<<<dim3(NG, 4), 512>>>(wpt);
    init_state<<<(2 * BATCH * H + 255) / 256, 256>>>(speed, pos);

    for (int t = 0; t < OBS; t++)
        lstm_cell<<<GRID, THREADS, DYN_SMEM>>>(0, speed + t * 4, pos + t * 4, OBS * 4, 0,
                                               t & 1, t, t == OBS - 1 ? 1 : 0);

    combine_state<<<(BATCH * H + 255) / 256, 256>>>();

    for (int t = 0; t < TDEC; t++) {
        lstm_cell<<<GRID, THREADS, DYN_SMEM>>>(2, nullptr, nullptr, 4, 1,
                                               t & 1, 16 + t, 0);
        proj_kernel<<<BATCH / 8, 256>>>(W_fs, b_fs, W_fc, b_fc, W_emb, b_emb, out, t, 1 - (t & 1));
    }
}

// round 10
// speedup vs baseline: 1.1723x; 1.1723x over previous
#include <cuda_runtime.h>
#include <cuda_fp16.h>
#include <cstdint>

#define BATCH 4096
#define OBS 16
#define TDEC 32
#define H 512
#define NG 2048
#define KC 64
#define NSTAGE 8             // 512/64
#define DEPTH 3
#define BM 128
#define BN 128
#define THREADS 256
#define STAGE_BYTES 32768    // A 16K | B 16K
#define TILE_BYTES 16384
#define TILE_HALF 8192
#define DYN_SMEM (DEPTH * STAGE_BYTES)   // 98304

// ---------------- device state ----------------
// h fp16, tiled+swizzled to match smem stage layout: [z][parity][my][stage][16KB]
__device__ __align__(16) __half  g_hT[2][2][32][8][TILE_HALF];
// weights fp16 tiled+swizzled: [lstm][nx][stage][16KB]
__device__ __align__(16) __half  g_WsT[4][16][8][TILE_HALF];
__device__ __align__(16) float   g_h[2][BATCH * H];   // fp32 h (last enc step -> combine)
__device__ __align__(16) float   g_c[2][BATCH * H];
__device__ __align__(16) float   g_Wi[4][NG * 4];
__device__ __align__(16) float   g_bb[4][NG];
__device__ __align__(16) float   g_ls[BATCH * 4];
__device__ __align__(16) float   g_lp[BATCH * 4];

// ---------------- helpers ----------------
__device__ __forceinline__ unsigned su32(const void* p) {
    return (unsigned)__cvta_generic_to_shared(p);
}
__device__ __forceinline__ unsigned swz(unsigned o) { return o ^ ((o >> 3) & 0x70); }
__device__ __forceinline__ float sigf(float x) { return 1.f / (1.f + __expf(-x)); }
__device__ __forceinline__ float tanhfast(float x) { return 2.f / (1.f + __expf(-2.f * x)) - 1.f; }

#define BAR_INIT(a, c) asm volatile("mbarrier.init.shared.b64 [%0], %1;" :: "r"(a), "r"(c) : "memory")
#define BAR_EXPECT(a, n) asm volatile("mbarrier.arrive.expect_tx.shared.b64 _, [%0], %1;" :: "r"(a), "r"(n) : "memory")
#define BAR_WAIT(a, p) do { unsigned d_ = 0; while (!d_) { \
    asm volatile("{\n\t.reg .pred p;\n\t" \
        "mbarrier.try_wait.parity.acquire.cta.shared::cta.b64 p, [%1], %2, 0x989680;\n\t" \
        "selp.b32 %0, 1, 0, p;\n\t}" : "=r"(d_) : "r"(a), "r"(p) : "memory"); } } while (0)

__device__ __forceinline__ void bulkcp(unsigned dst, const void* src, unsigned bytes, unsigned mbar) {
    asm volatile("cp.async.bulk.shared::cluster.global.mbarrier::complete_tx::bytes [%0], [%1], %2, [%3];"
        :: "r"(dst), "l"(src), "r"(bytes), "r"(mbar) : "memory");
}

// ---------------- weight prep: permute + tile + swizzle ----------------
struct WPtrs { const float* Wh[4]; const float* Wi[4]; const float* bb[4]; };

__global__ void prep_weights(WPtrs p) {
    int k = threadIdx.x, j = blockIdx.x, l = blockIdx.y;
    float w = p.Wh[l][j * H + k];
    int pr = 4 * (j & (H - 1)) + (j >> 9);   // 4u + gate
    int nx = pr >> 7, r = pr & 127;
    int sp = k >> 6, c = k & 63;
    char* tb = (char*)g_WsT[l][nx][sp];
    *(__half*)(tb + swz((unsigned)(r * 128 + c * 2))) = __float2half(w);
    if (k < 4)  g_Wi[l][pr * 4 + k] = p.Wi[l][j * 4 + k];
    if (k == 0) g_bb[l][pr] = p.bb[l][j];
}

__global__ void init_state(const float* speed, const float* pos) {
    int idx = blockIdx.x * blockDim.x + threadIdx.x;
    if (idx < 2 * BATCH * H) {
        int s = idx / (BATCH * H), i = idx % (BATCH * H);
        ((__half*)g_hT[s][0])[i] = __float2half(0.f);   // parity-0 tiles zeroed
        g_c[s][i] = 0.f;
    }
    if (idx < BATCH * 4) {
        int b = idx >> 2, k = idx & 3;
        g_ls[idx] = speed[b * (OBS * 4) + (OBS - 1) * 4 + k];
        g_lp[idx] = pos[b * (OBS * 4) + (OBS - 1) * 4 + k];
    }
}

__global__ void combine_state() {
    int i = blockIdx.x * blockDim.x + threadIdx.x;
    float hs = g_h[0][i] + g_h[1][i];
    float cs = g_c[0][i] + g_c[1][i];
    g_c[0][i] = cs; g_c[1][i] = cs;
    __half hv = __float2half(hs);
    int m = i >> 9, u = i & 511;
    unsigned off = swz((unsigned)((m & 127) * 128 + (u & 63) * 2));
    *(__half*)((char*)g_hT[0][0][m >> 7][u >> 6] + off) = hv;
    *(__half*)((char*)g_hT[1][0][m >> 7][u >> 6] + off) = hv;
}

// ---------------- fused LSTM cell: bulk-copy pipeline + fp16 mma.sync ----------------
__global__ void __launch_bounds__(THREADS, 2) lstm_cell(
    int lstm_base, const float* x0, const float* x1, int xstride, int internal_x,
    int rp, int write_h32)
{
    extern __shared__ char smem[];
    __shared__ float sB[BN];
    __shared__ float sWi[BN * 4];
    __shared__ __align__(8) uint64_t s_full[DEPTH];

    const int z = blockIdx.z;
    const int nx = blockIdx.x;
    const int my = blockIdx.y;
    const int lstm = lstm_base + z;
    const int wp = 1 - rp;
    const int n0 = nx * BN;
    const int m0 = my * BM;
    const int tid = threadIdx.x;
    const int lane = tid & 31, warp = tid >> 5;
    const int wmb = (warp & 1) * 64;
    const int wnb = (warp >> 1) * 32;

    const float* x = internal_x ? (z ? g_lp : g_ls) : (z ? x1 : x0);
    const char* Asrc = (const char*)g_hT[z][rp][my];      // + sp*16KB
    const char* Bsrc = (const char*)g_WsT[lstm][nx];      // + sp*16KB

    if (tid < DEPTH) BAR_INIT(su32(&s_full[tid]), 1u);
    if (tid < BN) {
        int n = n0 + tid;
        sB[tid] = g_bb[lstm][n];
        #pragma unroll
        for (int k = 0; k < 4; k++) sWi[tid * 4 + k] = g_Wi[lstm][n * 4 + k];
    }
    __syncthreads();

    auto produce = [&](int sp) {
        int sl = sp % DEPTH;
        unsigned mb = su32(&s_full[sl]);
        unsigned dst = su32(smem + sl * STAGE_BYTES);
        BAR_EXPECT(mb, (unsigned)STAGE_BYTES);
        bulkcp(dst,             Asrc + sp * TILE_BYTES, TILE_BYTES, mb);
        bulkcp(dst + TILE_BYTES, Bsrc + sp * TILE_BYTES, TILE_BYTES, mb);
    };

    if (tid == 0) { produce(0); produce(1); produce(2); }

    float acc[4][4][4] = {};

    for (int s = 0; s < NSTAGE; s++) {
        BAR_WAIT(su32(&s_full[s % DEPTH]), (unsigned)((s / DEPTH) & 1));

        const char* Ab = smem + (s % DEPTH) * STAGE_BYTES;
        const char* Bb = Ab + TILE_BYTES;
        #pragma unroll
        for (int kk = 0; kk < 4; kk++) {
            uint32_t a[4][4];
            #pragma unroll
            for (int im = 0; im < 4; im++) {
                int row = wmb + im * 16 + (lane & 15);
                unsigned off = swz(row * 128 + kk * 32 + ((lane >> 4) << 4));
                asm volatile("ldmatrix.sync.aligned.m8n8.x4.shared.b16 {%0,%1,%2,%3}, [%4];"
                    : "=r"(a[im][0]), "=r"(a[im][1]), "=r"(a[im][2]), "=r"(a[im][3])
                    : "r"(su32(Ab + off)));
            }
            uint32_t b[4][2];
            #pragma unroll
            for (int gp = 0; gp < 2; gp++) {
                int row = wnb + gp * 16 + ((lane >> 4) << 3) + (lane & 7);
                unsigned off = swz(row * 128 + kk * 32 + (((lane >> 3) & 1) << 4));
                asm volatile("ldmatrix.sync.aligned.m8n8.x4.shared.b16 {%0,%1,%2,%3}, [%4];"
                    : "=r"(b[2 * gp][0]), "=r"(b[2 * gp][1]),
                      "=r"(b[2 * gp + 1][0]), "=r"(b[2 * gp + 1][1])
                    : "r"(su32(Bb + off)));
            }
            #pragma unroll
            for (int im = 0; im < 4; im++)
                #pragma unroll
                for (int g = 0; g < 4; g++)
                    asm volatile("mma.sync.aligned.m16n8k16.row.col.f32.f16.f16.f32 "
                        "{%0,%1,%2,%3}, {%4,%5,%6,%7}, {%8,%9}, {%0,%1,%2,%3};"
                        : "+f"(acc[im][g][0]), "+f"(acc[im][g][1]),
                          "+f"(acc[im][g][2]), "+f"(acc[im][g][3])
                        : "r"(a[im][0]), "r"(a[im][1]), "r"(a[im][2]), "r"(a[im][3]),
                          "r"(b[g][0]), "r"(b[g][1]));
        }

        __syncthreads();                       // all consumers done with this slot
        if (tid == 0 && s + DEPTH < NSTAGE) produce(s + DEPTH);
    }

    // ---------------- epilogue ----------------
    float* Gs = (float*)smem;   // [128][132]
    #pragma unroll
    for (int im = 0; im < 4; im++)
        #pragma unroll
        for (int g = 0; g < 4; g++) {
            int r = wmb + im * 16 + (lane >> 2);
            int c = wnb + g * 8 + 2 * (lane & 3);
            Gs[r * 132 + c]           = acc[im][g][0];
            Gs[r * 132 + c + 1]       = acc[im][g][1];
            Gs[(r + 8) * 132 + c]     = acc[im][g][2];
            Gs[(r + 8) * 132 + c + 1] = acc[im][g][3];
        }
    __syncthreads();

    float* hout = g_h[z];
    float* cio  = g_c[z];
    char* hTw = (char*)g_hT[z][wp][my][nx >> 1];   // all this job's u fall in one stage tile
    const int u0g = n0 >> 2;
    const int colbase = (nx & 1) * 32;

    #pragma unroll 4
    for (int i = 0; i < 16; i++) {
        int p = tid + THREADS * i;
        int m = p >> 5, ul = p & 31;
        int mg = m0 + m;
        const float4 gv = *(const float4*)&Gs[m * 132 + 4 * ul];
        const float* xr = x + (size_t)mg * xstride;
        float xv0 = xr[0], xv1 = xr[1], xv2 = xr[2], xv3 = xr[3];
        float gate[4] = { gv.x, gv.y, gv.z, gv.w };
        #pragma unroll
        for (int q = 0; q < 4; q++) {
            int nn = 4 * ul + q;
            gate[q] += sB[nn] + xv0 * sWi[nn * 4 + 0] + xv1 * sWi[nn * 4 + 1]
                              + xv2 * sWi[nn * 4 + 2] + xv3 * sWi[nn * 4 + 3];
        }
        float iv = sigf(gate[0]);
        float fv = sigf(gate[1]);
        float gg = tanhfast(gate[2]);
        float ov = sigf(gate[3]);
        size_t ci = (size_t)mg * H + u0g + ul;
        float cn = fv * cio[ci] + iv * gg;
        float hn = ov * tanhfast(cn);
        cio[ci] = cn;
        if (write_h32) hout[ci] = hn;
        *(__half*)(hTw + swz((unsigned)(m * 128 + (colbase + ul) * 2))) = __float2half(hn);
    }
}

// ---------------- decoder projections + feedback (tiled fp16 h inputs) ----------------
__global__ void proj_kernel(const float* W_fs, const float* b_fs,
                            const float* W_fc, const float* b_fc,
                            const float* W_emb, const float* b_emb,
                            float* out, int t, int par)
{
    int warp = threadIdx.x >> 5, lane = threadIdx.x & 31;
    int b = blockIdx.x * 8 + warp;
    float a0 = 0, a1 = 0, a2 = 0, a3 = 0, a4 = 0, a5 = 0;
    unsigned off = swz((unsigned)((b & 127) * 128 + lane * 4));
    #pragma unroll
    for (int sp = 0; sp < 8; sp++) {
        float2 vs = __half22float2(*(const __half2*)((const char*)g_hT[0][par][b >> 7][sp] + off));
        float2 vi = __half22float2(*(const __half2*)((const char*)g_hT[1][par][b >> 7][sp] + off));
        int k = sp * 64 + lane * 2;
        a0 += vs.x * W_fs[k]         + vs.y * W_fs[k + 1];
        a1 += vs.x * W_fs[H + k]     + vs.y * W_fs[H + k + 1];
        a2 += vs.x * W_fs[2 * H + k] + vs.y * W_fs[2 * H + k + 1];
        a3 += vs.x * W_fs[3 * H + k] + vs.y * W_fs[3 * H + k + 1];
        a4 += vi.x * W_fc[k]         + vi.y * W_fc[k + 1];
        a5 += vi.x * W_fc[H + k]     + vi.y * W_fc[H + k + 1];
    }
    #pragma unroll
    for (int o = 16; o; o >>= 1) {
        a0 += __shfl_down_sync(0xffffffffu, a0, o);
        a1 += __shfl_down_sync(0xffffffffu, a1, o);
        a2 += __shfl_down_sync(0xffffffffu, a2, o);
        a3 += __shfl_down_sync(0xffffffffu, a3, o);
        a4 += __shfl_down_sync(0xffffffffu, a4, o);
        a5 += __shfl_down_sync(0xffffffffu, a5, o);
    }
    if (lane == 0) {
        float4 spv;
        spv.x = fminf(fmaxf(a0 + b_fs[0], -100.f), 100.f);
        spv.y = fminf(fmaxf(a1 + b_fs[1], -100.f), 100.f);
        spv.z = fminf(fmaxf(a2 + b_fs[2], -100.f), 100.f);
        spv.w = fminf(fmaxf(a3 + b_fs[3], -100.f), 100.f);
        float it0 = fmaxf(a4 + b_fc[0], 0.f);
        float it1 = fmaxf(a5 + b_fc[1], 0.f);
        *(float4*)&out[((size_t)b * TDEC + t) * 4] = spv;
        *(float4*)&g_ls[b * 4] = spv;
        float4 lpv;
        lpv.x = fmaxf(W_emb[0] * it0 + W_emb[1] * it1 + b_emb[0], 0.f);
        lpv.y = fmaxf(W_emb[2] * it0 + W_emb[3] * it1 + b_emb[1], 0.f);
        lpv.z = fmaxf(W_emb[4] * it0 + W_emb[5] * it1 + b_emb[2], 0.f);
        lpv.w = fmaxf(W_emb[6] * it0 + W_emb[7] * it1 + b_emb[3], 0.f);
        *(float4*)&g_lp[b * 4] = lpv;
        if (t == TDEC - 1) {
            float mx = fmaxf(it0, it1);
            float e0 = expf(it0 - mx), e1 = expf(it1 - mx);
            float s = e0 + e1;
            out[(size_t)BATCH * TDEC * 4 + b * 2]     = e0 / s;
            out[(size_t)BATCH * TDEC * 4 + b * 2 + 1] = e1 / s;
        }
    }
}

// ---------------- launch ----------------
extern "C" void kernel_launch(void* const* d_in, const int* in_sizes, int n_in,
                              void* d_out, int out_size)
{
    const float* speed = (const float*)d_in[0];
    const float* pos   = (const float*)d_in[1];
    WPtrs wpt;
    wpt.Wi[0] = (const float*)d_in[2];  wpt.Wh[0] = (const float*)d_in[3];  wpt.bb[0] = (const float*)d_in[4];
    wpt.Wi[1] = (const float*)d_in[5];  wpt.Wh[1] = (const float*)d_in[6];  wpt.bb[1] = (const float*)d_in[7];
    wpt.Wi[2] = (const float*)d_in[8];  wpt.Wh[2] = (const float*)d_in[9];  wpt.bb[2] = (const float*)d_in[10];
    wpt.Wi[3] = (const float*)d_in[11]; wpt.Wh[3] = (const float*)d_in[12]; wpt.bb[3] = (const float*)d_in[13];
    const float* W_fs  = (const float*)d_in[14];
    const float* b_fs  = (const float*)d_in[15];
    const float* W_fc  = (const float*)d_in[16];
    const float* b_fc  = (const float*)d_in[17];
    const float* W_emb = (const float*)d_in[18];
    const float* b_emb = (const float*)d_in[19];
    float* out = (float*)d_out;

    cudaFuncSetAttribute(lstm_cell, cudaFuncAttributeMaxDynamicSharedMemorySize, DYN_SMEM);

    prep_weights<<<dim3(NG, 4), 512>>>(wpt);
    init_state<<<(2 * BATCH * H + 255) / 256, 256>>>(speed, pos);

    dim3 cgrid(NG / BN, BATCH / BM, 2);   // (16, 32, 2)
    for (int t = 0; t < OBS; t++)
        lstm_cell<<<cgrid, THREADS, DYN_SMEM>>>(0, speed + t * 4, pos + t * 4, OBS * 4, 0,
                                                t & 1, t == OBS - 1 ? 1 : 0);

    combine_state<<<(BATCH * H + 255) / 256, 256>>>();

    for (int t = 0; t < TDEC; t++) {
        lstm_cell<<<cgrid, THREADS, DYN_SMEM>>>(2, nullptr, nullptr, 4, 1, t & 1, 0);
        proj_kernel<<<BATCH / 8, 256>>>(W_fs, b_fs, W_fc, b_fc, W_emb, b_emb, out, t, 1 - (t & 1));
    }
}

// round 11
// speedup vs baseline: 1.4259x; 1.2163x over previous
#include <cuda_runtime.h>
#include <cuda_fp16.h>
#include <cstdint>

#define BATCH 4096
#define OBS 16
#define TDEC 32
#define H 512
#define NG 2048
#define KC 64
#define NSTAGE 8             // 512/64
#define DEPTH 3
#define BM 128
#define BN 128
#define THREADS 256
#define STAGE_BYTES 32768    // A 16K | B 16K
#define TILE_BYTES 16384
#define TILE_HALF 8192
#define DYN_SMEM (DEPTH * STAGE_BYTES)   // 98304

// ---------------- device state ----------------
__device__ __align__(16) __half  g_hT[2][2][32][8][TILE_HALF];  // tiled+swizzled h
__device__ __align__(16) __half  g_WsT[4][16][8][TILE_HALF];    // tiled+swizzled W
__device__ __align__(16) float   g_h[2][BATCH * H];   // fp32 h (last enc step -> combine)
__device__ __align__(16) float   g_c[2][BATCH * H];
__device__ __align__(16) float   g_Wi[4][NG * 4];
__device__ __align__(16) float   g_bb[4][NG];
__device__ __align__(16) float   g_ls[BATCH * 4];
__device__ __align__(16) float   g_lp[BATCH * 4];

// ---------------- helpers ----------------
__device__ __forceinline__ unsigned su32(const void* p) {
    return (unsigned)__cvta_generic_to_shared(p);
}
__device__ __forceinline__ unsigned swz(unsigned o) { return o ^ ((o >> 3) & 0x70); }
__device__ __forceinline__ float sigf(float x) { return 1.f / (1.f + __expf(-x)); }
__device__ __forceinline__ float tanhfast(float x) { return 2.f / (1.f + __expf(-2.f * x)) - 1.f; }

#define BAR_INIT(a, c) asm volatile("mbarrier.init.shared.b64 [%0], %1;" :: "r"(a), "r"(c) : "memory")
#define BAR_EXPECT(a, n) asm volatile("mbarrier.arrive.expect_tx.shared.b64 _, [%0], %1;" :: "r"(a), "r"(n) : "memory")
#define BAR_WAIT(a, p) do { unsigned d_ = 0; while (!d_) { \
    asm volatile("{\n\t.reg .pred p;\n\t" \
        "mbarrier.try_wait.parity.acquire.cta.shared::cta.b64 p, [%1], %2, 0x989680;\n\t" \
        "selp.b32 %0, 1, 0, p;\n\t}" : "=r"(d_) : "r"(a), "r"(p) : "memory"); } } while (0)

__device__ __forceinline__ void bulkcp(unsigned dst, const void* src, unsigned bytes, unsigned mbar) {
    asm volatile("cp.async.bulk.shared::cluster.global.mbarrier::complete_tx::bytes [%0], [%1], %2, [%3];"
        :: "r"(dst), "l"(src), "r"(bytes), "r"(mbar) : "memory");
}

// ---------------- weight prep: permute + tile + swizzle ----------------
struct WPtrs { const float* Wh[4]; const float* Wi[4]; const float* bb[4]; };

__global__ void prep_weights(WPtrs p) {
    int k = threadIdx.x, j = blockIdx.x, l = blockIdx.y;
    float w = p.Wh[l][j * H + k];
    int pr = 4 * (j & (H - 1)) + (j >> 9);   // 4u + gate
    int nx = pr >> 7, r = pr & 127;
    int sp = k >> 6, c = k & 63;
    char* tb = (char*)g_WsT[l][nx][sp];
    *(__half*)(tb + swz((unsigned)(r * 128 + c * 2))) = __float2half(w);
    if (k < 4)  g_Wi[l][pr * 4 + k] = p.Wi[l][j * 4 + k];
    if (k == 0) g_bb[l][pr] = p.bb[l][j];
}

__global__ void init_state(const float* speed, const float* pos) {
    int idx = blockIdx.x * blockDim.x + threadIdx.x;
    if (idx < 2 * BATCH * H) {
        int s = idx / (BATCH * H), i = idx % (BATCH * H);
        ((__half*)g_hT[s][0])[i] = __float2half(0.f);
        g_c[s][i] = 0.f;
    }
    if (idx < BATCH * 4) {
        int b = idx >> 2, k = idx & 3;
        g_ls[idx] = speed[b * (OBS * 4) + (OBS - 1) * 4 + k];
        g_lp[idx] = pos[b * (OBS * 4) + (OBS - 1) * 4 + k];
    }
}

__global__ void combine_state() {
    int i = blockIdx.x * blockDim.x + threadIdx.x;
    float hs = g_h[0][i] + g_h[1][i];
    float cs = g_c[0][i] + g_c[1][i];
    g_c[0][i] = cs; g_c[1][i] = cs;
    __half hv = __float2half(hs);
    int m = i >> 9, u = i & 511;
    unsigned off = swz((unsigned)((m & 127) * 128 + (u & 63) * 2));
    *(__half*)((char*)g_hT[0][0][m >> 7][u >> 6] + off) = hv;
    *(__half*)((char*)g_hT[1][0][m >> 7][u >> 6] + off) = hv;
}

// ---------------- fused LSTM cell: bulk-copy pipeline + fp16 mma.sync ----------------
__global__ void __launch_bounds__(THREADS, 2) lstm_cell(
    int lstm_base, const float* x0, const float* x1, int xstride, int internal_x,
    int rp, int write_h32)
{
    extern __shared__ char smem[];
    __shared__ float sB[BN];
    __shared__ float sWi[BN * 4];
    __shared__ __align__(8) uint64_t s_full[DEPTH];

    const int z = blockIdx.z;
    const int nx = blockIdx.x;
    const int my = blockIdx.y;
    const int lstm = lstm_base + z;
    const int wp = 1 - rp;
    const int n0 = nx * BN;
    const int m0 = my * BM;
    const int tid = threadIdx.x;
    const int lane = tid & 31, warp = tid >> 5;
    const int wmb = (warp & 1) * 64;
    const int wnb = (warp >> 1) * 32;

    const float* x = internal_x ? (z ? g_lp : g_ls) : (z ? x1 : x0);
    const char* Asrc = (const char*)g_hT[z][rp][my];
    const char* Bsrc = (const char*)g_WsT[lstm][nx];

    if (tid < DEPTH) BAR_INIT(su32(&s_full[tid]), 1u);
    if (tid < BN) {
        int n = n0 + tid;
        sB[tid] = g_bb[lstm][n];
        #pragma unroll
        for (int k = 0; k < 4; k++) sWi[tid * 4 + k] = g_Wi[lstm][n * 4 + k];
    }
    __syncthreads();

    auto produce = [&](int sp) {
        int sl = sp % DEPTH;
        unsigned mb = su32(&s_full[sl]);
        unsigned dst = su32(smem + sl * STAGE_BYTES);
        BAR_EXPECT(mb, (unsigned)STAGE_BYTES);
        bulkcp(dst,              Asrc + sp * TILE_BYTES, TILE_BYTES, mb);
        bulkcp(dst + TILE_BYTES, Bsrc + sp * TILE_BYTES, TILE_BYTES, mb);
    };

    if (tid == 0) { produce(0); produce(1); produce(2); }

    float acc[4][4][4] = {};

    for (int s = 0; s < NSTAGE; s++) {
        BAR_WAIT(su32(&s_full[s % DEPTH]), (unsigned)((s / DEPTH) & 1));

        const char* Ab = smem + (s % DEPTH) * STAGE_BYTES;
        const char* Bb = Ab + TILE_BYTES;
        #pragma unroll
        for (int kk = 0; kk < 4; kk++) {
            uint32_t a[4][4];
            #pragma unroll
            for (int im = 0; im < 4; im++) {
                int row = wmb + im * 16 + (lane & 15);
                unsigned off = swz(row * 128 + kk * 32 + ((lane >> 4) << 4));
                asm volatile("ldmatrix.sync.aligned.m8n8.x4.shared.b16 {%0,%1,%2,%3}, [%4];"
                    : "=r"(a[im][0]), "=r"(a[im][1]), "=r"(a[im][2]), "=r"(a[im][3])
                    : "r"(su32(Ab + off)));
            }
            uint32_t b[4][2];
            #pragma unroll
            for (int gp = 0; gp < 2; gp++) {
                int row = wnb + gp * 16 + ((lane >> 4) << 3) + (lane & 7);
                unsigned off = swz(row * 128 + kk * 32 + (((lane >> 3) & 1) << 4));
                asm volatile("ldmatrix.sync.aligned.m8n8.x4.shared.b16 {%0,%1,%2,%3}, [%4];"
                    : "=r"(b[2 * gp][0]), "=r"(b[2 * gp][1]),
                      "=r"(b[2 * gp + 1][0]), "=r"(b[2 * gp + 1][1])
                    : "r"(su32(Bb + off)));
            }
            #pragma unroll
            for (int im = 0; im < 4; im++)
                #pragma unroll
                for (int g = 0; g < 4; g++)
                    asm volatile("mma.sync.aligned.m16n8k16.row.col.f32.f16.f16.f32 "
                        "{%0,%1,%2,%3}, {%4,%5,%6,%7}, {%8,%9}, {%0,%1,%2,%3};"
                        : "+f"(acc[im][g][0]), "+f"(acc[im][g][1]),
                          "+f"(acc[im][g][2]), "+f"(acc[im][g][3])
                        : "r"(a[im][0]), "r"(a[im][1]), "r"(a[im][2]), "r"(a[im][3]),
                          "r"(b[g][0]), "r"(b[g][1]));
        }

        __syncthreads();
        if (tid == 0 && s + DEPTH < NSTAGE) produce(s + DEPTH);
    }

    // ---------------- epilogue: transpose, then one batch-row per thread ----------------
    float* Gs = (float*)smem;   // [128][132]
    #pragma unroll
    for (int im = 0; im < 4; im++)
        #pragma unroll
        for (int g = 0; g < 4; g++) {
            int r = wmb + im * 16 + (lane >> 2);
            int c = wnb + g * 8 + 2 * (lane & 3);
            Gs[r * 132 + c]           = acc[im][g][0];
            Gs[r * 132 + c + 1]       = acc[im][g][1];
            Gs[(r + 8) * 132 + c]     = acc[im][g][2];
            Gs[(r + 8) * 132 + c + 1] = acc[im][g][3];
        }
    __syncthreads();

    {
        const int m = tid >> 1;          // batch row within tile
        const int half = tid & 1;        // low/high 16 hidden units
        const int mg = m0 + m;
        const int u0g = n0 >> 2;
        const int colbase = (nx & 1) * 32;

        const float* xr = x + (size_t)mg * xstride;
        const float xv0 = xr[0], xv1 = xr[1], xv2 = xr[2], xv3 = xr[3];

        float* crow = g_c[z] + (size_t)mg * H + u0g + half * 16;
        float* hrow = g_h[z] + (size_t)mg * H + u0g + half * 16;
        char* hTw = (char*)g_hT[z][wp][my][nx >> 1];

        float cold[16];
        #pragma unroll
        for (int q = 0; q < 4; q++) *(float4*)&cold[4 * q] = *(const float4*)&crow[4 * q];

        float cnew[16], hnew[16];
        #pragma unroll
        for (int j = 0; j < 16; j++) {
            int ul = half * 16 + j;
            int nn = 4 * ul;
            const float4 gv = *(const float4*)&Gs[m * 132 + nn];
            const float4 w0 = *(const float4*)&sWi[(nn + 0) * 4];
            const float4 w1 = *(const float4*)&sWi[(nn + 1) * 4];
            const float4 w2 = *(const float4*)&sWi[(nn + 2) * 4];
            const float4 w3 = *(const float4*)&sWi[(nn + 3) * 4];
            const float4 bv = *(const float4*)&sB[nn];
            float g0 = gv.x + bv.x + xv0 * w0.x + xv1 * w0.y + xv2 * w0.z + xv3 * w0.w;
            float g1 = gv.y + bv.y + xv0 * w1.x + xv1 * w1.y + xv2 * w1.z + xv3 * w1.w;
            float g2 = gv.z + bv.z + xv0 * w2.x + xv1 * w2.y + xv2 * w2.z + xv3 * w2.w;
            float g3 = gv.w + bv.w + xv0 * w3.x + xv1 * w3.y + xv2 * w3.z + xv3 * w3.w;
            float iv = sigf(g0);
            float fv = sigf(g1);
            float gg = tanhfast(g2);
            float ov = sigf(g3);
            float cn = fv * cold[j] + iv * gg;
            cnew[j] = cn;
            hnew[j] = ov * tanhfast(cn);
        }
        #pragma unroll
        for (int q = 0; q < 4; q++) *(float4*)&crow[4 * q] = *(const float4*)&cnew[4 * q];
        if (write_h32) {
            #pragma unroll
            for (int q = 0; q < 4; q++) *(float4*)&hrow[4 * q] = *(const float4*)&hnew[4 * q];
        }
        // pack 16 halves -> two swizzled 16B stores
        uint4 pk[2];
        unsigned* pw = (unsigned*)pk;
        #pragma unroll
        for (int q = 0; q < 8; q++) {
            __half2 hp = __floats2half2_rn(hnew[2 * q], hnew[2 * q + 1]);
            pw[q] = *(unsigned*)&hp;
        }
        unsigned base = (unsigned)(m * 128 + colbase * 2 + half * 32);
        *(uint4*)(hTw + swz(base))      = pk[0];
        *(uint4*)(hTw + swz(base + 16)) = pk[1];
    }
}

// ---------------- decoder projections + feedback (1 wave: 128 CTAs x 32 warps) ----------------
__global__ void __launch_bounds__(1024) proj_kernel(
    const float* W_fs, const float* b_fs,
    const float* W_fc, const float* b_fc,
    const float* W_emb, const float* b_emb,
    float* out, int t, int par)
{
    int warp = threadIdx.x >> 5, lane = threadIdx.x & 31;
    int b = blockIdx.x * 32 + warp;
    float a0 = 0, a1 = 0, a2 = 0, a3 = 0, a4 = 0, a5 = 0;
    unsigned off = swz((unsigned)((b & 127) * 128 + lane * 4));
    #pragma unroll
    for (int sp = 0; sp < 8; sp++) {
        float2 vs = __half22float2(*(const __half2*)((const char*)g_hT[0][par][b >> 7][sp] + off));
        float2 vi = __half22float2(*(const __half2*)((const char*)g_hT[1][par][b >> 7][sp] + off));
        int k = sp * 64 + lane * 2;
        a0 += vs.x * W_fs[k]         + vs.y * W_fs[k + 1];
        a1 += vs.x * W_fs[H + k]     + vs.y * W_fs[H + k + 1];
        a2 += vs.x * W_fs[2 * H + k] + vs.y * W_fs[2 * H + k + 1];
        a3 += vs.x * W_fs[3 * H + k] + vs.y * W_fs[3 * H + k + 1];
        a4 += vi.x * W_fc[k]         + vi.y * W_fc[k + 1];
        a5 += vi.x * W_fc[H + k]     + vi.y * W_fc[H + k + 1];
    }
    #pragma unroll
    for (int o = 16; o; o >>= 1) {
        a0 += __shfl_down_sync(0xffffffffu, a0, o);
        a1 += __shfl_down_sync(0xffffffffu, a1, o);
        a2 += __shfl_down_sync(0xffffffffu, a2, o);
        a3 += __shfl_down_sync(0xffffffffu, a3, o);
        a4 += __shfl_down_sync(0xffffffffu, a4, o);
        a5 += __shfl_down_sync(0xffffffffu, a5, o);
    }
    if (lane == 0) {
        float4 spv;
        spv.x = fminf(fmaxf(a0 + b_fs[0], -100.f), 100.f);
        spv.y = fminf(fmaxf(a1 + b_fs[1], -100.f), 100.f);
        spv.z = fminf(fmaxf(a2 + b_fs[2], -100.f), 100.f);
        spv.w = fminf(fmaxf(a3 + b_fs[3], -100.f), 100.f);
        float it0 = fmaxf(a4 + b_fc[0], 0.f);
        float it1 = fmaxf(a5 + b_fc[1], 0.f);
        *(float4*)&out[((size_t)b * TDEC + t) * 4] = spv;
        *(float4*)&g_ls[b * 4] = spv;
        float4 lpv;
        lpv.x = fmaxf(W_emb[0] * it0 + W_emb[1] * it1 + b_emb[0], 0.f);
        lpv.y = fmaxf(W_emb[2] * it0 + W_emb[3] * it1 + b_emb[1], 0.f);
        lpv.z = fmaxf(W_emb[4] * it0 + W_emb[5] * it1 + b_emb[2], 0.f);
        lpv.w = fmaxf(W_emb[6] * it0 + W_emb[7] * it1 + b_emb[3], 0.f);
        *(float4*)&g_lp[b * 4] = lpv;
        if (t == TDEC - 1) {
            float mx = fmaxf(it0, it1);
            float e0 = expf(it0 - mx), e1 = expf(it1 - mx);
            float s = e0 + e1;
            out[(size_t)BATCH * TDEC * 4 + b * 2]     = e0 / s;
            out[(size_t)BATCH * TDEC * 4 + b * 2 + 1] = e1 / s;
        }
    }
}

// ---------------- launch ----------------
extern "C" void kernel_launch(void* const* d_in, const int* in_sizes, int n_in,
                              void* d_out, int out_size)
{
    const float* speed = (const float*)d_in[0];
    const float* pos   = (const float*)d_in[1];
    WPtrs wpt;
    wpt.Wi[0] = (const float*)d_in[2];  wpt.Wh[0] = (const float*)d_in[3];  wpt.bb[0] = (const float*)d_in[4];
    wpt.Wi[1] = (const float*)d_in[5];  wpt.Wh[1] = (const float*)d_in[6];  wpt.bb[1] = (const float*)d_in[7];
    wpt.Wi[2] = (const float*)d_in[8];  wpt.Wh[2] = (const float*)d_in[9];  wpt.bb[2] = (const float*)d_in[10];
    wpt.Wi[3] = (const float*)d_in[11]; wpt.Wh[3] = (const float*)d_in[12]; wpt.bb[3] = (const float*)d_in[13];
    const float* W_fs  = (const float*)d_in[14];
    const float* b_fs  = (const float*)d_in[15];
    const float* W_fc  = (const float*)d_in[16];
    const float* b_fc  = (const float*)d_in[17];
    const float* W_emb = (const float*)d_in[18];
    const float* b_emb = (const float*)d_in[19];
    float* out = (float*)d_out;

    cudaFuncSetAttribute(lstm_cell, cudaFuncAttributeMaxDynamicSharedMemorySize, DYN_SMEM);

    prep_weights<<<dim3(NG, 4), 512>>>(wpt);
    init_state<<<(2 * BATCH * H + 255) / 256, 256>>>(speed, pos);

    dim3 cgrid(NG / BN, BATCH / BM, 2);   // (16, 32, 2)
    for (int t = 0; t < OBS; t++)
        lstm_cell<<<cgrid, THREADS, DYN_SMEM>>>(0, speed + t * 4, pos + t * 4, OBS * 4, 0,
                                                t & 1, t == OBS - 1 ? 1 : 0);

    combine_state<<<(BATCH * H + 255) / 256, 256>>>();

    for (int t = 0; t < TDEC; t++) {
        lstm_cell<<<cgrid, THREADS, DYN_SMEM>>>(2, nullptr, nullptr, 4, 1, t & 1, 0);
        proj_kernel<<<BATCH / 32, 1024>>>(W_fs, b_fs, W_fc, b_fc, W_emb, b_emb, out, t, 1 - (t & 1));
    }
}